// round 12
// baseline (speedup 1.0000x reference)
#include <cuda_runtime.h>
#include <cuda_fp16.h>
#include <cstdint>

// ---------------------------------------------------------------------------
// Problem constants
// ---------------------------------------------------------------------------
#define M_DIM 16384   // B*S = 8*2048
#define N_DIM 4096    // OUT
#define K_DIM 4096    // IN
#define KE    4224    // extended K: 4096 + 8 adapters * 16 rank
#define BK    64
#define KT_CNT 66     // KE / 64
#define S_LEN 2048
#define R_RANK 16

// Block ranges in the fused prep kernel
#define NB_T 512            // lora_t blocks
#define NB_A 32768          // ext_a real-K blocks: 128 mtiles * 64 ktiles * 4
#define NB_B 8448           // ext_b blocks: 32 ntiles * 66 ktiles * 4
#define NB_TOTAL (NB_T + NB_A + NB_B)

// ---------------------------------------------------------------------------
// Device-global scratch
//  g_t  : t = x @ lora_a^T, fp32 [M, 16]
//  g_xe : A image, fp16 + K-extended + FRAGMENT-PACKED (m16n8k16 layout)
//         [mtile(128)][ktile(66)] x 16KB tiles (8192 halves)
//  g_we : B image likewise: [ntile(32)][ktile(66)] x 16KB tiles
// ---------------------------------------------------------------------------
__device__ __align__(16) float g_t[M_DIM * R_RANK];
__device__ __align__(1024) __half g_xe[(size_t)128 * KT_CNT * 8192];
__device__ __align__(1024) __half g_we[(size_t)32  * KT_CNT * 8192];

__device__ __forceinline__ uint32_t pack2(float lo, float hi) {
    __half2 h = __floats2half2_rn(lo, hi);
    return *(uint32_t*)&h;
}

// ---------------------------------------------------------------------------
// Fused prepass kernel: three INDEPENDENT jobs selected by blockIdx.x.
//   [0, NB_T)              : t = x @ lora_a^T  (fp32, exact)
//   [NB_T, NB_T+NB_A)      : A image, real-K ktiles only (no g_t dependency)
//   [NB_T+NB_A, NB_TOTAL)  : B image, all ktiles (lora_b ext has no g_t dep)
// ---------------------------------------------------------------------------
__global__ __launch_bounds__(256) void prep_fused_kernel(const float* __restrict__ x,
                                                         const float* __restrict__ la,
                                                         const float* __restrict__ W,
                                                         const float* __restrict__ lb) {
    const uint32_t b = blockIdx.x;
    const int tid = threadIdx.x;

    if (b < NB_T) {
        // ---------------- lora_t ----------------
        const int warp = tid >> 5;
        const int lane = tid & 31;
        const int m0 = b * 32 + warp * 4;
        const int adapter = m0 / S_LEN;
        const float* lap = la + (size_t)adapter * R_RANK * K_DIM;

        float acc[4][R_RANK];
#pragma unroll
        for (int rr = 0; rr < 4; rr++)
#pragma unroll
            for (int r = 0; r < R_RANK; r++) acc[rr][r] = 0.f;

        for (int kk = lane; kk < K_DIM / 4; kk += 32) {
            const int k = kk * 4;
            float4 xv[4];
#pragma unroll
            for (int rr = 0; rr < 4; rr++)
                xv[rr] = *(const float4*)(x + (size_t)(m0 + rr) * K_DIM + k);
#pragma unroll
            for (int r = 0; r < R_RANK; r++) {
                const float4 av = *(const float4*)(lap + (size_t)r * K_DIM + k);
#pragma unroll
                for (int rr = 0; rr < 4; rr++) {
                    acc[rr][r] += xv[rr].x * av.x;
                    acc[rr][r] += xv[rr].y * av.y;
                    acc[rr][r] += xv[rr].z * av.z;
                    acc[rr][r] += xv[rr].w * av.w;
                }
            }
        }
#pragma unroll
        for (int off = 16; off > 0; off >>= 1)
#pragma unroll
            for (int rr = 0; rr < 4; rr++)
#pragma unroll
                for (int r = 0; r < R_RANK; r++)
                    acc[rr][r] += __shfl_xor_sync(0xffffffffu, acc[rr][r], off);
        if (lane < R_RANK) {
#pragma unroll
            for (int rr = 0; rr < 4; rr++)
                g_t[(m0 + rr) * R_RANK + lane] = acc[rr][lane];
        }
    } else if (b < NB_T + NB_A) {
        // ---------------- ext_a, real-K ktiles ----------------
        const uint32_t idx = (b - NB_T) * 256 + tid;   // < 128*64*1024
        const uint32_t u = idx & 1023;
        const uint32_t t2 = idx >> 10;                 // mtile*64 + ktile
        const uint32_t mtile = t2 >> 6;
        const uint32_t ktile = t2 & 63;

        const uint32_t lane = u & 31;
        const uint32_t ks = (u >> 5) & 3;
        const uint32_t mt = (u >> 7) & 3;
        const uint32_t wm = (u >> 9) & 1;
        const uint32_t g = lane >> 2, tg = lane & 3;

        const uint32_t m0 = mtile * 128 + wm * 64 + mt * 16 + g;  // rows m0, m0+8
        const uint32_t k0 = ktile * 64 + ks * 16 + 2 * tg;

        const float2 p00 = *(const float2*)(x + (size_t)m0 * K_DIM + k0);
        const float2 p10 = *(const float2*)(x + (size_t)(m0 + 8) * K_DIM + k0);
        const float2 p01 = *(const float2*)(x + (size_t)m0 * K_DIM + k0 + 8);
        const float2 p11 = *(const float2*)(x + (size_t)(m0 + 8) * K_DIM + k0 + 8);
        uint4 v;
        v.x = pack2(p00.x, p00.y);
        v.y = pack2(p10.x, p10.y);
        v.z = pack2(p01.x, p01.y);
        v.w = pack2(p11.x, p11.y);
        *(uint4*)(g_xe + (size_t)(mtile * KT_CNT + ktile) * 8192 + u * 8) = v;
    } else {
        // ---------------- ext_b, all ktiles ----------------
        const uint32_t idx = (b - NB_T - NB_A) * 256 + tid;  // < 32*66*1024
        const uint32_t u = idx & 1023;
        const uint32_t tile = idx >> 10;                     // ntile*66 + ktile
        const uint32_t ntile = tile / KT_CNT;
        const uint32_t ktile = tile % KT_CNT;

        const uint32_t lane = u & 31;
        const uint32_t ks = (u >> 5) & 3;
        const uint32_t ntp = (u >> 7) & 1;
        const uint32_t wn = (u >> 8) & 3;
        const uint32_t g = lane >> 2, tg = lane & 3;

        const uint32_t c0 = ntile * 128 + wn * 32 + ntp * 16 + g;  // cols c0, c0+8
        const uint32_t k0 = ktile * 64 + ks * 16 + 2 * tg;

        uint4 v;
        if (k0 < K_DIM) {
            const float2 p00 = *(const float2*)(W + (size_t)c0 * K_DIM + k0);
            const float2 p01 = *(const float2*)(W + (size_t)c0 * K_DIM + k0 + 8);
            const float2 p10 = *(const float2*)(W + (size_t)(c0 + 8) * K_DIM + k0);
            const float2 p11 = *(const float2*)(W + (size_t)(c0 + 8) * K_DIM + k0 + 8);
            v.x = pack2(p00.x, p00.y);
            v.y = pack2(p01.x, p01.y);
            v.z = pack2(p10.x, p10.y);
            v.w = pack2(p11.x, p11.y);
        } else {
            const uint32_t e = k0 - K_DIM;
            const uint32_t a = e >> 4, r = e & 15;
            const float* p0 = lb + ((size_t)a * N_DIM + c0) * R_RANK;
            const float* p1 = lb + ((size_t)a * N_DIM + c0 + 8) * R_RANK;
            v.x = pack2(p0[r], p0[r + 1]);
            v.y = pack2(p0[r + 8], p0[r + 9]);
            v.z = pack2(p1[r], p1[r + 1]);
            v.w = pack2(p1[r + 8], p1[r + 9]);
        }
        *(uint4*)(g_we + (size_t)tile * 8192 + u * 8) = v;
    }
}

// ---------------------------------------------------------------------------
// A-image extension tail (ktiles 64,65) — needs FINAL g_t. Tiny (256 blocks).
// ---------------------------------------------------------------------------
__global__ __launch_bounds__(256) void ext_a_tail_kernel() {
    const int tid = threadIdx.x;
    const uint32_t kt = 64 + blockIdx.x;    // 64 or 65
    const uint32_t mtile = blockIdx.y;

    __half* dst = g_xe + (size_t)(mtile * KT_CNT + kt) * 8192;
#pragma unroll
    for (int j = 0; j < 4; j++) {
        const uint32_t u = tid + j * 256;
        const uint32_t lane = u & 31;
        const uint32_t ks = (u >> 5) & 3;
        const uint32_t mt = (u >> 7) & 3;
        const uint32_t wm = (u >> 9) & 1;
        const uint32_t g = lane >> 2, tg = lane & 3;

        const uint32_t m0 = mtile * 128 + wm * 64 + mt * 16 + g;
        const uint32_t k0 = kt * 64 + ks * 16 + 2 * tg;
        const uint32_t e = k0 - K_DIM;      // pairs stay inside one 16-chunk
        const uint32_t a = e >> 4, r = e & 15;
        const uint32_t ad = m0 >> 11;

        uint4 v = make_uint4(0, 0, 0, 0);
        if (a == ad) {
            const float2 t00 = *(const float2*)(g_t + (size_t)m0 * R_RANK + r);
            const float2 t10 = *(const float2*)(g_t + (size_t)(m0 + 8) * R_RANK + r);
            const float2 t01 = *(const float2*)(g_t + (size_t)m0 * R_RANK + r + 8);
            const float2 t11 = *(const float2*)(g_t + (size_t)(m0 + 8) * R_RANK + r + 8);
            v.x = pack2(2.f * t00.x, 2.f * t00.y);
            v.y = pack2(2.f * t10.x, 2.f * t10.y);
            v.z = pack2(2.f * t01.x, 2.f * t01.y);
            v.w = pack2(2.f * t11.x, 2.f * t11.y);
        }
        *(uint4*)(dst + u * 8) = v;
    }
}

// ---------------------------------------------------------------------------
// GEMM — R5 config (known-good): 128x128x64 tiles, fp16 m16n8k16, f32 accum,
// fragment-packed smem, 3-stage cp.async pipeline, 2 CTAs/SM.
// Per warp-ktile: 24 LDS.128 + 64 MMA.
// ---------------------------------------------------------------------------
#define STAGES 3
#define TILE_BYTES 16384
#define STAGE_BYTES (2 * TILE_BYTES)          // A + B = 32KB
#define SMEM_BYTES (STAGES * STAGE_BYTES)     // 98304

__device__ __forceinline__ void mma_f16(float* c, const uint32_t* a, const uint32_t* b) {
    asm volatile(
        "mma.sync.aligned.m16n8k16.row.col.f32.f16.f16.f32 "
        "{%0,%1,%2,%3}, {%4,%5,%6,%7}, {%8,%9}, {%0,%1,%2,%3};"
        : "+f"(c[0]), "+f"(c[1]), "+f"(c[2]), "+f"(c[3])
        : "r"(a[0]), "r"(a[1]), "r"(a[2]), "r"(a[3]), "r"(b[0]), "r"(b[1]));
}

__global__ __launch_bounds__(256, 2) void lora_gemm_kernel(float* __restrict__ out) {
    extern __shared__ char smem[];
    const int tid = threadIdx.x;
    const int lane = tid & 31;
    const int warp = tid >> 5;
    const int warp_m = warp >> 2;   // 0..1
    const int warp_n = warp & 3;    // 0..3
    const int g = lane >> 2;
    const int tg = lane & 3;
    const uint32_t mtile = blockIdx.y;
    const uint32_t ntile = blockIdx.x;

    float acc[4][4][4];
#pragma unroll
    for (int mt = 0; mt < 4; mt++)
#pragma unroll
        for (int nt = 0; nt < 4; nt++)
#pragma unroll
            for (int c = 0; c < 4; c++) acc[mt][nt][c] = 0.f;

    const char* gA = (const char*)g_xe + ((size_t)mtile * KT_CNT << 14);
    const char* gB = (const char*)g_we + ((size_t)ntile * KT_CNT << 14);

    auto load_tile = [&](int stage, int kt) {
        char* st = smem + stage * STAGE_BYTES;
        const char* sa = gA + ((size_t)kt << 14);
        const char* sb = gB + ((size_t)kt << 14);
#pragma unroll
        for (int i = 0; i < 4; i++) {
            const int off = (tid + i * 256) * 16;
            uint32_t dA = (uint32_t)__cvta_generic_to_shared(st + off);
            asm volatile("cp.async.cg.shared.global [%0], [%1], 16;" ::"r"(dA), "l"(sa + off));
            uint32_t dB = (uint32_t)__cvta_generic_to_shared(st + TILE_BYTES + off);
            asm volatile("cp.async.cg.shared.global [%0], [%1], 16;" ::"r"(dB), "l"(sb + off));
        }
    };

    auto compute_tile = [&](int stage) {
        const char* sA = smem + stage * STAGE_BYTES;
        const char* sB = sA + TILE_BYTES;
#pragma unroll
        for (int ks = 0; ks < 4; ks++) {
            uint4 af[4];
#pragma unroll
            for (int mt = 0; mt < 4; mt++)
                af[mt] = *(const uint4*)(sA + (((warp_m * 4 + mt) * 4 + ks) * 32 + lane) * 16);
            uint4 bv[2];
#pragma unroll
            for (int ntp = 0; ntp < 2; ntp++)
                bv[ntp] = *(const uint4*)(sB + (((warp_n * 2 + ntp) * 4 + ks) * 32 + lane) * 16);
            uint32_t bf[4][2];
#pragma unroll
            for (int ntp = 0; ntp < 2; ntp++) {
                bf[2 * ntp][0] = bv[ntp].x;
                bf[2 * ntp][1] = bv[ntp].y;
                bf[2 * ntp + 1][0] = bv[ntp].z;
                bf[2 * ntp + 1][1] = bv[ntp].w;
            }
#pragma unroll
            for (int mt = 0; mt < 4; mt++)
#pragma unroll
                for (int nt = 0; nt < 4; nt++)
                    mma_f16(acc[mt][nt], (const uint32_t*)&af[mt], bf[nt]);
        }
    };

#pragma unroll
    for (int s = 0; s < STAGES - 1; s++) {
        load_tile(s, s);
        asm volatile("cp.async.commit_group;");
    }
    for (int kt = 0; kt < KT_CNT; kt++) {
        asm volatile("cp.async.wait_group %0;" ::"n"(STAGES - 2));
        __syncthreads();
        const int nxt = kt + STAGES - 1;
        if (nxt < KT_CNT) load_tile(nxt % STAGES, nxt);
        asm volatile("cp.async.commit_group;");
        compute_tile(kt % STAGES);
    }

    // ---- pure-store epilogue (LoRA already folded into K) ----
#pragma unroll
    for (int mt = 0; mt < 4; mt++)
#pragma unroll
        for (int i = 0; i < 2; i++) {
            const size_t row = (size_t)mtile * 128 + warp_m * 64 + mt * 16 + g + i * 8;
#pragma unroll
            for (int nt = 0; nt < 4; nt++) {
                const uint32_t col = ntile * 128 + warp_n * 32 + nt * 8 + tg * 2;
                *(float2*)&out[row * N_DIM + col] =
                    make_float2(acc[mt][nt][i * 2 + 0], acc[mt][nt][i * 2 + 1]);
            }
        }
}

// ---------------------------------------------------------------------------
// Harness entry
// d_in[0]=data [8,2048,4096] f32, d_in[1]=W [4096,4096] f32,
// d_in[2]=lora_a [8,16,4096] f32, d_in[3]=lora_b [8,4096,16] f32
// ---------------------------------------------------------------------------
extern "C" void kernel_launch(void* const* d_in, const int* in_sizes, int n_in,
                              void* d_out, int out_size) {
    const float* x = (const float*)d_in[0];
    const float* W = (const float*)d_in[1];
    const float* la = (const float*)d_in[2];
    const float* lb = (const float*)d_in[3];
    float* out = (float*)d_out;

    cudaFuncSetAttribute(lora_gemm_kernel,
                         cudaFuncAttributeMaxDynamicSharedMemorySize, SMEM_BYTES);

    prep_fused_kernel<<<NB_TOTAL, 256>>>(x, la, W, lb);   // t + A(real-K) + B
    {
        dim3 gt(2, M_DIM / 128);                          // A extension ktiles
        ext_a_tail_kernel<<<gt, 256>>>();
    }
    dim3 grid(N_DIM / 128, M_DIM / 128);                  // (32, 128)
    lora_gemm_kernel<<<grid, 256, SMEM_BYTES>>>(out);
}

// round 15
// speedup vs baseline: 1.5468x; 1.5468x over previous
#include <cuda_runtime.h>
#include <cuda_fp16.h>
#include <cstdint>

// ---------------------------------------------------------------------------
// Problem constants
// ---------------------------------------------------------------------------
#define M_DIM 16384   // B*S = 8*2048
#define N_DIM 4096    // OUT
#define K_DIM 4096    // IN
#define KE    4224    // extended K: 4096 + 8 adapters * 16 rank
#define BK    64
#define KT_CNT 66     // KE / 64
#define S_LEN 2048
#define R_RANK 16

// ---------------------------------------------------------------------------
// Device-global scratch
//  g_t  : t = x @ lora_a^T, fp32 [M, 16]
//  g_xe : A image, fp16 + K-extended + FRAGMENT-PACKED (m16n8k16 layout)
//         [mtile(128)][ktile(66)] x 16KB tiles (8192 halves)
//  g_we : B image likewise: [ntile(32)][ktile(66)] x 16KB tiles
// ---------------------------------------------------------------------------
__device__ __align__(16) float g_t[M_DIM * R_RANK];
__device__ __align__(1024) __half g_xe[(size_t)128 * KT_CNT * 8192];
__device__ __align__(1024) __half g_we[(size_t)32  * KT_CNT * 8192];

__device__ __forceinline__ uint32_t pack2(float lo, float hi) {
    __half2 h = __floats2half2_rn(lo, hi);
    return *(uint32_t*)&h;
}

// ---------------------------------------------------------------------------
// Kernel 1: t[m, r] = sum_k x[m,k] * lora_a[adapter(m)][r][k]   (fp32 exact)
// (R5 verbatim — measured-good)
// ---------------------------------------------------------------------------
__global__ __launch_bounds__(256) void lora_t_kernel(const float* __restrict__ x,
                                                     const float* __restrict__ la) {
    const int warp = threadIdx.x >> 5;
    const int lane = threadIdx.x & 31;
    const int m0 = blockIdx.x * 32 + warp * 4;
    const int adapter = m0 / S_LEN;
    const float* lap = la + (size_t)adapter * R_RANK * K_DIM;

    float acc[4][R_RANK];
#pragma unroll
    for (int rr = 0; rr < 4; rr++)
#pragma unroll
        for (int r = 0; r < R_RANK; r++) acc[rr][r] = 0.f;

    for (int kk = lane; kk < K_DIM / 4; kk += 32) {
        const int k = kk * 4;
        float4 xv[4];
#pragma unroll
        for (int rr = 0; rr < 4; rr++)
            xv[rr] = *(const float4*)(x + (size_t)(m0 + rr) * K_DIM + k);
#pragma unroll
        for (int r = 0; r < R_RANK; r++) {
            const float4 av = *(const float4*)(lap + (size_t)r * K_DIM + k);
#pragma unroll
            for (int rr = 0; rr < 4; rr++) {
                acc[rr][r] += xv[rr].x * av.x;
                acc[rr][r] += xv[rr].y * av.y;
                acc[rr][r] += xv[rr].z * av.z;
                acc[rr][r] += xv[rr].w * av.w;
            }
        }
    }
#pragma unroll
    for (int off = 16; off > 0; off >>= 1)
#pragma unroll
        for (int rr = 0; rr < 4; rr++)
#pragma unroll
            for (int r = 0; r < R_RANK; r++)
                acc[rr][r] += __shfl_xor_sync(0xffffffffu, acc[rr][r], off);
    if (lane < R_RANK) {
#pragma unroll
        for (int rr = 0; rr < 4; rr++)
            g_t[(m0 + rr) * R_RANK + lane] = acc[rr][lane];
    }
}

// ---------------------------------------------------------------------------
// Kernel 2: build A image — SMEM-STAGED (coalesced x reads).
// One block = one (mtile, ktile): stage 128x64 f32 -> smem, then emit 1024
// fragment-packed fp16 16B units coalesced. Extension ktiles fill from g_t.
// sx padded to 68 floats/row: 272B stride, 16B-aligned rows.
// ---------------------------------------------------------------------------
__global__ __launch_bounds__(256) void ext_a_kernel(const float* __restrict__ x) {
    __shared__ __align__(16) float sx[128][68];
    const int tid = threadIdx.x;
    const uint32_t ktile = blockIdx.x;       // 0..65
    const uint32_t mtile = blockIdx.y;       // 0..127
    const uint32_t k0 = ktile * 64;
    const uint32_t ad = mtile >> 4;          // adapter uniform over tile

    if (k0 < K_DIM) {
#pragma unroll
        for (int i = 0; i < 8; i++) {
            const int idx = tid + i * 256;   // 2048 float4 slots
            const int row = idx >> 4;
            const int c4 = (idx & 15) * 4;
            const float4 v = *(const float4*)(x + (size_t)(mtile * 128 + row) * K_DIM + k0 + c4);
            *(float4*)&sx[row][c4] = v;
        }
    } else {
#pragma unroll
        for (int i = 0; i < 8; i++) {
            const int idx = tid + i * 256;
            const int row = idx >> 4;
            const int c4 = (idx & 15) * 4;
            const uint32_t e = k0 + c4 - K_DIM;   // 16-aligned: one adapter slot
            const uint32_t a = e >> 4, r = e & 15;
            float4 v = make_float4(0.f, 0.f, 0.f, 0.f);
            if (a == ad) {
                const float4 t = *(const float4*)(g_t + (size_t)(mtile * 128 + row) * R_RANK + r);
                v = make_float4(2.f * t.x, 2.f * t.y, 2.f * t.z, 2.f * t.w);
            }
            *(float4*)&sx[row][c4] = v;
        }
    }
    __syncthreads();

    __half* dst = g_xe + (size_t)(mtile * KT_CNT + ktile) * 8192;
#pragma unroll
    for (int j = 0; j < 4; j++) {
        const uint32_t u = tid + j * 256;
        const uint32_t lane = u & 31;
        const uint32_t ks = (u >> 5) & 3;
        const uint32_t mt = (u >> 7) & 3;
        const uint32_t wm = (u >> 9) & 1;
        const uint32_t g = lane >> 2, tg = lane & 3;
        const uint32_t r0 = wm * 64 + mt * 16 + g;
        const uint32_t kk = ks * 16 + 2 * tg;

        const float2 p00 = *(const float2*)&sx[r0][kk];
        const float2 p10 = *(const float2*)&sx[r0 + 8][kk];
        const float2 p01 = *(const float2*)&sx[r0][kk + 8];
        const float2 p11 = *(const float2*)&sx[r0 + 8][kk + 8];
        uint4 v;
        v.x = pack2(p00.x, p00.y);
        v.y = pack2(p10.x, p10.y);
        v.z = pack2(p01.x, p01.y);
        v.w = pack2(p11.x, p11.y);
        *(uint4*)(dst + u * 8) = v;
    }
}

// ---------------------------------------------------------------------------
// Kernel 3: build B image — SMEM-STAGED (coalesced W reads); measured 28us.
// Extension ktiles read lora_b directly (tiny, L2-resident).
// ---------------------------------------------------------------------------
__global__ __launch_bounds__(256) void ext_b_kernel(const float* __restrict__ W,
                                                    const float* __restrict__ lb) {
    __shared__ __align__(16) float sw[128][68];
    const int tid = threadIdx.x;
    const uint32_t ktile = blockIdx.x;   // 0..65
    const uint32_t ntile = blockIdx.y;   // 0..31
    const uint32_t k0b = ktile * 64;
    __half* dst = g_we + (size_t)(ntile * KT_CNT + ktile) * 8192;

    if (k0b < K_DIM) {
#pragma unroll
        for (int i = 0; i < 8; i++) {
            const int idx = tid + i * 256;
            const int row = idx >> 4;          // col index within 128
            const int c4 = (idx & 15) * 4;
            const float4 v =
                *(const float4*)(W + (size_t)(ntile * 128 + row) * K_DIM + k0b + c4);
            *(float4*)&sw[row][c4] = v;
        }
        __syncthreads();
#pragma unroll
        for (int j = 0; j < 4; j++) {
            const uint32_t u = tid + j * 256;
            const uint32_t lane = u & 31;
            const uint32_t ks = (u >> 5) & 3;
            const uint32_t ntp = (u >> 7) & 1;
            const uint32_t wn = (u >> 8) & 3;
            const uint32_t g = lane >> 2, tg = lane & 3;
            const uint32_t c0 = wn * 32 + ntp * 16 + g;    // local col, c0 and c0+8
            const uint32_t kk = ks * 16 + 2 * tg;

            const float2 p00 = *(const float2*)&sw[c0][kk];
            const float2 p01 = *(const float2*)&sw[c0][kk + 8];
            const float2 p10 = *(const float2*)&sw[c0 + 8][kk];
            const float2 p11 = *(const float2*)&sw[c0 + 8][kk + 8];
            uint4 v;
            v.x = pack2(p00.x, p00.y);
            v.y = pack2(p01.x, p01.y);
            v.z = pack2(p10.x, p10.y);
            v.w = pack2(p11.x, p11.y);
            *(uint4*)(dst + u * 8) = v;
        }
    } else {
#pragma unroll
        for (int j = 0; j < 4; j++) {
            const uint32_t u = tid + j * 256;
            const uint32_t lane = u & 31;
            const uint32_t ks = (u >> 5) & 3;
            const uint32_t ntp = (u >> 7) & 1;
            const uint32_t wn = (u >> 8) & 3;
            const uint32_t g = lane >> 2, tg = lane & 3;
            const uint32_t c0 = ntile * 128 + wn * 32 + ntp * 16 + g;
            const uint32_t k0 = k0b + ks * 16 + 2 * tg;
            const uint32_t e = k0 - K_DIM;
            const uint32_t a = e >> 4, r = e & 15;
            const float* p0 = lb + ((size_t)a * N_DIM + c0) * R_RANK;
            const float* p1 = lb + ((size_t)a * N_DIM + c0 + 8) * R_RANK;
            uint4 v;
            v.x = pack2(p0[r], p0[r + 1]);
            v.y = pack2(p0[r + 8], p0[r + 9]);
            v.z = pack2(p1[r], p1[r + 1]);
            v.w = pack2(p1[r + 8], p1[r + 9]);
            *(uint4*)(dst + u * 8) = v;
        }
    }
}

// ---------------------------------------------------------------------------
// Kernel 4: GEMM — R5 config verbatim (measured 1204us, tensor 77.5%):
// 128x128x64 tiles, fp16 m16n8k16 (f32 accum), fragment-packed smem,
// 3-stage cp.async pipeline, 2 CTAs/SM. Per warp-ktile: 24 LDS.128 + 64 MMA.
// ---------------------------------------------------------------------------
#define STAGES 3
#define TILE_BYTES 16384
#define STAGE_BYTES (2 * TILE_BYTES)          // A + B = 32KB
#define SMEM_BYTES (STAGES * STAGE_BYTES)     // 98304

__device__ __forceinline__ void mma_f16(float* c, const uint32_t* a, const uint32_t* b) {
    asm volatile(
        "mma.sync.aligned.m16n8k16.row.col.f32.f16.f16.f32 "
        "{%0,%1,%2,%3}, {%4,%5,%6,%7}, {%8,%9}, {%0,%1,%2,%3};"
        : "+f"(c[0]), "+f"(c[1]), "+f"(c[2]), "+f"(c[3])
        : "r"(a[0]), "r"(a[1]), "r"(a[2]), "r"(a[3]), "r"(b[0]), "r"(b[1]));
}

__global__ __launch_bounds__(256, 2) void lora_gemm_kernel(float* __restrict__ out) {
    extern __shared__ char smem[];
    const int tid = threadIdx.x;
    const int lane = tid & 31;
    const int warp = tid >> 5;
    const int warp_m = warp >> 2;   // 0..1
    const int warp_n = warp & 3;    // 0..3
    const int g = lane >> 2;
    const int tg = lane & 3;
    const uint32_t mtile = blockIdx.y;
    const uint32_t ntile = blockIdx.x;

    float acc[4][4][4];
#pragma unroll
    for (int mt = 0; mt < 4; mt++)
#pragma unroll
        for (int nt = 0; nt < 4; nt++)
#pragma unroll
            for (int c = 0; c < 4; c++) acc[mt][nt][c] = 0.f;

    const char* gA = (const char*)g_xe + ((size_t)mtile * KT_CNT << 14);
    const char* gB = (const char*)g_we + ((size_t)ntile * KT_CNT << 14);

    auto load_tile = [&](int stage, int kt) {
        char* st = smem + stage * STAGE_BYTES;
        const char* sa = gA + ((size_t)kt << 14);
        const char* sb = gB + ((size_t)kt << 14);
#pragma unroll
        for (int i = 0; i < 4; i++) {
            const int off = (tid + i * 256) * 16;
            uint32_t dA = (uint32_t)__cvta_generic_to_shared(st + off);
            asm volatile("cp.async.cg.shared.global [%0], [%1], 16;" ::"r"(dA), "l"(sa + off));
            uint32_t dB = (uint32_t)__cvta_generic_to_shared(st + TILE_BYTES + off);
            asm volatile("cp.async.cg.shared.global [%0], [%1], 16;" ::"r"(dB), "l"(sb + off));
        }
    };

    auto compute_tile = [&](int stage) {
        const char* sA = smem + stage * STAGE_BYTES;
        const char* sB = sA + TILE_BYTES;
#pragma unroll
        for (int ks = 0; ks < 4; ks++) {
            uint4 af[4];
#pragma unroll
            for (int mt = 0; mt < 4; mt++)
                af[mt] = *(const uint4*)(sA + (((warp_m * 4 + mt) * 4 + ks) * 32 + lane) * 16);
            uint4 bv[2];
#pragma unroll
            for (int ntp = 0; ntp < 2; ntp++)
                bv[ntp] = *(const uint4*)(sB + (((warp_n * 2 + ntp) * 4 + ks) * 32 + lane) * 16);
            uint32_t bf[4][2];
#pragma unroll
            for (int ntp = 0; ntp < 2; ntp++) {
                bf[2 * ntp][0] = bv[ntp].x;
                bf[2 * ntp][1] = bv[ntp].y;
                bf[2 * ntp + 1][0] = bv[ntp].z;
                bf[2 * ntp + 1][1] = bv[ntp].w;
            }
#pragma unroll
            for (int mt = 0; mt < 4; mt++)
#pragma unroll
                for (int nt = 0; nt < 4; nt++)
                    mma_f16(acc[mt][nt], (const uint32_t*)&af[mt], bf[nt]);
        }
    };

#pragma unroll
    for (int s = 0; s < STAGES - 1; s++) {
        load_tile(s, s);
        asm volatile("cp.async.commit_group;");
    }
    for (int kt = 0; kt < KT_CNT; kt++) {
        asm volatile("cp.async.wait_group %0;" ::"n"(STAGES - 2));
        __syncthreads();
        const int nxt = kt + STAGES - 1;
        if (nxt < KT_CNT) load_tile(nxt % STAGES, nxt);
        asm volatile("cp.async.commit_group;");
        compute_tile(kt % STAGES);
    }

    // ---- pure-store epilogue (LoRA already folded into K) ----
#pragma unroll
    for (int mt = 0; mt < 4; mt++)
#pragma unroll
        for (int i = 0; i < 2; i++) {
            const size_t row = (size_t)mtile * 128 + warp_m * 64 + mt * 16 + g + i * 8;
#pragma unroll
            for (int nt = 0; nt < 4; nt++) {
                const uint32_t col = ntile * 128 + warp_n * 32 + nt * 8 + tg * 2;
                *(float2*)&out[row * N_DIM + col] =
                    make_float2(acc[mt][nt][i * 2 + 0], acc[mt][nt][i * 2 + 1]);
            }
        }
}

// ---------------------------------------------------------------------------
// Harness entry
// d_in[0]=data [8,2048,4096] f32, d_in[1]=W [4096,4096] f32,
// d_in[2]=lora_a [8,16,4096] f32, d_in[3]=lora_b [8,4096,16] f32
// ---------------------------------------------------------------------------
extern "C" void kernel_launch(void* const* d_in, const int* in_sizes, int n_in,
                              void* d_out, int out_size) {
    const float* x = (const float*)d_in[0];
    const float* W = (const float*)d_in[1];
    const float* la = (const float*)d_in[2];
    const float* lb = (const float*)d_in[3];
    float* out = (float*)d_out;

    cudaFuncSetAttribute(lora_gemm_kernel,
                         cudaFuncAttributeMaxDynamicSharedMemorySize, SMEM_BYTES);

    lora_t_kernel<<<M_DIM / 32, 256>>>(x, la);
    {
        dim3 ga(KT_CNT, M_DIM / 128);    // staged A image (incl. ext ktiles)
        ext_a_kernel<<<ga, 256>>>(x);
    }
    {
        dim3 gb(KT_CNT, N_DIM / 128);    // staged B image
        ext_b_kernel<<<gb, 256>>>(W, lb);
    }
    dim3 grid(N_DIM / 128, M_DIM / 128); // (32, 128)
    lora_gemm_kernel<<<grid, 256, SMEM_BYTES>>>(out);
}

// round 16
// speedup vs baseline: 1.7528x; 1.1331x over previous
#include <cuda_runtime.h>
#include <cuda_fp16.h>
#include <cstdint>

// ---------------------------------------------------------------------------
// Problem constants
// ---------------------------------------------------------------------------
#define M_DIM 16384   // B*S = 8*2048
#define N_DIM 4096    // OUT
#define K_DIM 4096    // IN
#define KE    4224    // extended K: 4096 + 8 adapters * 16 rank
#define BK    64
#define KT_CNT 66     // KE / 64
#define S_LEN 2048
#define R_RANK 16

// ---------------------------------------------------------------------------
// Device-global scratch
//  g_t  : t = x @ lora_a^T, fp32 [M, 16]
//  g_xe : A image, fp16 + K-extended + FRAGMENT-PACKED (m16n8k16 layout)
//         [mtile(128)][ktile(66)] x 16KB tiles (8192 halves)
//  g_we : B image likewise: [ntile(32)][ktile(66)] x 16KB tiles
// ---------------------------------------------------------------------------
__device__ __align__(16) float g_t[M_DIM * R_RANK];
__device__ __align__(1024) __half g_xe[(size_t)128 * KT_CNT * 8192];
__device__ __align__(1024) __half g_we[(size_t)32  * KT_CNT * 8192];

__device__ __forceinline__ uint32_t pack2(float lo, float hi) {
    __half2 h = __floats2half2_rn(lo, hi);
    return *(uint32_t*)&h;
}

// ---------------------------------------------------------------------------
// mbarrier / bulk-copy helpers (sm_90 features, sm_103-base legal)
// ---------------------------------------------------------------------------
#define MBAR_INIT(a, c) \
    asm volatile("mbarrier.init.shared.b64 [%0], %1;" :: "r"(a), "r"((uint32_t)(c)) : "memory")
#define MBAR_ARRIVE(a) \
    asm volatile("mbarrier.arrive.shared.b64 _, [%0];" :: "r"(a) : "memory")
#define MBAR_EXPECT_TX(a, b) \
    asm volatile("mbarrier.arrive.expect_tx.shared.b64 _, [%0], %1;" :: "r"(a), "r"((uint32_t)(b)) : "memory")
#define MBAR_WAIT(a, ph) do {                                                   \
    uint32_t _m = (a), _p = (uint32_t)(ph), _d;                                 \
    asm volatile("{\n\t.reg .pred p;\n\t"                                       \
        "mbarrier.try_wait.parity.acquire.cta.shared::cta.b64 p, [%1], %2;\n\t" \
        "selp.b32 %0, 1, 0, p;\n\t}" : "=r"(_d) : "r"(_m), "r"(_p) : "memory"); \
    if (!_d) {                                                                  \
        asm volatile("{\n\t.reg .pred P1;\n\tWL_%=:\n\t"                        \
            "mbarrier.try_wait.parity.acquire.cta.shared::cta.b64 P1, [%0], %1, 0x989680;\n\t" \
            "@P1 bra.uni WD_%=;\n\tbra.uni WL_%=;\n\tWD_%=:\n\t}"               \
            :: "r"(_m), "r"(_p) : "memory");                                    \
    }                                                                           \
} while (0)
#define BULK_G2S(dst, src, bytes, mbar)                                          \
    asm volatile(                                                                \
        "cp.async.bulk.shared::cta.global.mbarrier::complete_tx::bytes "         \
        "[%0], [%1], %2, [%3];"                                                  \
        :: "r"(dst), "l"(src), "r"((uint32_t)(bytes)), "r"(mbar) : "memory")

// ---------------------------------------------------------------------------
// Kernel 1: t[m, r] = sum_k x[m,k] * lora_a[adapter(m)][r][k]   (fp32 exact)
// (R5 verbatim — measured-good)
// ---------------------------------------------------------------------------
__global__ __launch_bounds__(256) void lora_t_kernel(const float* __restrict__ x,
                                                     const float* __restrict__ la) {
    const int warp = threadIdx.x >> 5;
    const int lane = threadIdx.x & 31;
    const int m0 = blockIdx.x * 32 + warp * 4;
    const int adapter = m0 / S_LEN;
    const float* lap = la + (size_t)adapter * R_RANK * K_DIM;

    float acc[4][R_RANK];
#pragma unroll
    for (int rr = 0; rr < 4; rr++)
#pragma unroll
        for (int r = 0; r < R_RANK; r++) acc[rr][r] = 0.f;

    for (int kk = lane; kk < K_DIM / 4; kk += 32) {
        const int k = kk * 4;
        float4 xv[4];
#pragma unroll
        for (int rr = 0; rr < 4; rr++)
            xv[rr] = *(const float4*)(x + (size_t)(m0 + rr) * K_DIM + k);
#pragma unroll
        for (int r = 0; r < R_RANK; r++) {
            const float4 av = *(const float4*)(lap + (size_t)r * K_DIM + k);
#pragma unroll
            for (int rr = 0; rr < 4; rr++) {
                acc[rr][r] += xv[rr].x * av.x;
                acc[rr][r] += xv[rr].y * av.y;
                acc[rr][r] += xv[rr].z * av.z;
                acc[rr][r] += xv[rr].w * av.w;
            }
        }
    }
#pragma unroll
    for (int off = 16; off > 0; off >>= 1)
#pragma unroll
        for (int rr = 0; rr < 4; rr++)
#pragma unroll
            for (int r = 0; r < R_RANK; r++)
                acc[rr][r] += __shfl_xor_sync(0xffffffffu, acc[rr][r], off);
    if (lane < R_RANK) {
#pragma unroll
        for (int rr = 0; rr < 4; rr++)
            g_t[(m0 + rr) * R_RANK + lane] = acc[rr][lane];
    }
}

// ---------------------------------------------------------------------------
// Kernel 2: build A image (R5 verbatim — strided, measured-good)
// one thread = one 16B unit (= one A fragment: a0..a3)
// ---------------------------------------------------------------------------
__global__ __launch_bounds__(256) void ext_a_kernel(const float* __restrict__ x) {
    const uint32_t idx = blockIdx.x * 256 + threadIdx.x;  // < 128*66*1024
    const uint32_t u = idx & 1023;
    const uint32_t tile = idx >> 10;
    const uint32_t mtile = tile / KT_CNT;
    const uint32_t ktile = tile % KT_CNT;

    const uint32_t lane = u & 31;
    const uint32_t ks = (u >> 5) & 3;
    const uint32_t mt = (u >> 7) & 3;
    const uint32_t wm = (u >> 9) & 1;
    const uint32_t g = lane >> 2, tg = lane & 3;

    const uint32_t m0 = mtile * 128 + wm * 64 + mt * 16 + g;  // rows m0, m0+8
    const uint32_t k0 = ktile * 64 + ks * 16 + 2 * tg;        // k0,k0+1,k0+8,k0+9

    uint4 v;
    if (k0 < K_DIM) {
        const float2 p00 = *(const float2*)(x + (size_t)m0 * K_DIM + k0);
        const float2 p10 = *(const float2*)(x + (size_t)(m0 + 8) * K_DIM + k0);
        const float2 p01 = *(const float2*)(x + (size_t)m0 * K_DIM + k0 + 8);
        const float2 p11 = *(const float2*)(x + (size_t)(m0 + 8) * K_DIM + k0 + 8);
        v.x = pack2(p00.x, p00.y);
        v.y = pack2(p10.x, p10.y);
        v.z = pack2(p01.x, p01.y);
        v.w = pack2(p11.x, p11.y);
    } else {
        const uint32_t e = k0 - K_DIM;        // pairs stay inside one 16-chunk
        const uint32_t a = e >> 4, r = e & 15;
        const uint32_t ad = m0 >> 11;         // adapter uniform over the tile
        if (a == ad) {
            const float2 t00 = *(const float2*)(g_t + (size_t)m0 * R_RANK + r);
            const float2 t10 = *(const float2*)(g_t + (size_t)(m0 + 8) * R_RANK + r);
            const float2 t01 = *(const float2*)(g_t + (size_t)m0 * R_RANK + r + 8);
            const float2 t11 = *(const float2*)(g_t + (size_t)(m0 + 8) * R_RANK + r + 8);
            v.x = pack2(2.f * t00.x, 2.f * t00.y);
            v.y = pack2(2.f * t10.x, 2.f * t10.y);
            v.z = pack2(2.f * t01.x, 2.f * t01.y);
            v.w = pack2(2.f * t11.x, 2.f * t11.y);
        } else {
            v = make_uint4(0, 0, 0, 0);
        }
    }
    *(uint4*)(g_xe + (size_t)tile * 8192 + u * 8) = v;
}

// ---------------------------------------------------------------------------
// Kernel 3: build B image (R5 verbatim — strided, measured-good)
// ---------------------------------------------------------------------------
__global__ __launch_bounds__(256) void ext_b_kernel(const float* __restrict__ W,
                                                    const float* __restrict__ lb) {
    const uint32_t idx = blockIdx.x * 256 + threadIdx.x;  // < 32*66*1024
    const uint32_t u = idx & 1023;
    const uint32_t tile = idx >> 10;
    const uint32_t ntile = tile / KT_CNT;
    const uint32_t ktile = tile % KT_CNT;

    const uint32_t lane = u & 31;
    const uint32_t ks = (u >> 5) & 3;
    const uint32_t ntp = (u >> 7) & 1;
    const uint32_t wn = (u >> 8) & 3;
    const uint32_t g = lane >> 2, tg = lane & 3;

    const uint32_t c0 = ntile * 128 + wn * 32 + ntp * 16 + g;  // cols c0, c0+8
    const uint32_t k0 = ktile * 64 + ks * 16 + 2 * tg;

    uint4 v;
    if (k0 < K_DIM) {
        const float2 p00 = *(const float2*)(W + (size_t)c0 * K_DIM + k0);
        const float2 p01 = *(const float2*)(W + (size_t)c0 * K_DIM + k0 + 8);
        const float2 p10 = *(const float2*)(W + (size_t)(c0 + 8) * K_DIM + k0);
        const float2 p11 = *(const float2*)(W + (size_t)(c0 + 8) * K_DIM + k0 + 8);
        v.x = pack2(p00.x, p00.y);
        v.y = pack2(p01.x, p01.y);
        v.z = pack2(p10.x, p10.y);
        v.w = pack2(p11.x, p11.y);
    } else {
        const uint32_t e = k0 - K_DIM;
        const uint32_t a = e >> 4, r = e & 15;
        const float* p0 = lb + ((size_t)a * N_DIM + c0) * R_RANK;
        const float* p1 = lb + ((size_t)a * N_DIM + c0 + 8) * R_RANK;
        v.x = pack2(p0[r], p0[r + 1]);
        v.y = pack2(p0[r + 8], p0[r + 9]);
        v.z = pack2(p1[r], p1[r + 1]);
        v.w = pack2(p1[r + 8], p1[r + 9]);
    }
    *(uint4*)(g_we + (size_t)tile * 8192 + u * 8) = v;
}

// ---------------------------------------------------------------------------
// Kernel 4: GEMM. 128x128x64 tiles, fp16 m16n8k16 (f32 accum), fragment-
// packed smem, 3-stage pipeline fed by cp.async.bulk (2 instr/stage instead
// of 2048 LDGSTS) + mbarrier full/empty pairs. 2 CTAs/SM.
// ---------------------------------------------------------------------------
#define STAGES 3
#define TILE_BYTES 16384
#define STAGE_BYTES (2 * TILE_BYTES)               // A + B = 32KB
#define BAR_BYTES 64
#define SMEM_BYTES (STAGES * STAGE_BYTES + BAR_BYTES)   // 98368

__device__ __forceinline__ void mma_f16(float* c, const uint32_t* a, const uint32_t* b) {
    asm volatile(
        "mma.sync.aligned.m16n8k16.row.col.f32.f16.f16.f32 "
        "{%0,%1,%2,%3}, {%4,%5,%6,%7}, {%8,%9}, {%0,%1,%2,%3};"
        : "+f"(c[0]), "+f"(c[1]), "+f"(c[2]), "+f"(c[3])
        : "r"(a[0]), "r"(a[1]), "r"(a[2]), "r"(a[3]), "r"(b[0]), "r"(b[1]));
}

__global__ __launch_bounds__(256, 2) void lora_gemm_kernel(float* __restrict__ out) {
    extern __shared__ char smem[];
    const int tid = threadIdx.x;
    const int lane = tid & 31;
    const int warp = tid >> 5;
    const int warp_m = warp >> 2;   // 0..1
    const int warp_n = warp & 3;    // 0..3
    const int g = lane >> 2;
    const int tg = lane & 3;
    const uint32_t mtile = blockIdx.y;
    const uint32_t ntile = blockIdx.x;

    const uint32_t bar0 = (uint32_t)__cvta_generic_to_shared(smem + STAGES * STAGE_BYTES);
    // full[s] = bar0 + s*8 ; empty[s] = bar0 + 24 + s*8

    float acc[4][4][4];
#pragma unroll
    for (int mt = 0; mt < 4; mt++)
#pragma unroll
        for (int nt = 0; nt < 4; nt++)
#pragma unroll
            for (int c = 0; c < 4; c++) acc[mt][nt][c] = 0.f;

    const char* gA = (const char*)g_xe + ((size_t)mtile * KT_CNT << 14);
    const char* gB = (const char*)g_we + ((size_t)ntile * KT_CNT << 14);

    if (tid == 0) {
#pragma unroll
        for (int s = 0; s < STAGES; s++) {
            MBAR_INIT(bar0 + s * 8, 1);        // full: 1 expect_tx arrival
            MBAR_INIT(bar0 + 24 + s * 8, 8);   // empty: one arrive per warp
        }
    }
    __syncthreads();

    auto issue_tile = [&](int s, int kt) {
        const uint32_t full = bar0 + s * 8;
        const uint32_t st = (uint32_t)__cvta_generic_to_shared(smem + s * STAGE_BYTES);
        MBAR_EXPECT_TX(full, STAGE_BYTES);
        BULK_G2S(st, gA + ((size_t)kt << 14), TILE_BYTES, full);
        BULK_G2S(st + TILE_BYTES, gB + ((size_t)kt << 14), TILE_BYTES, full);
    };

    if (tid == 0) {
        issue_tile(0, 0);
        issue_tile(1, 1);
    }

    auto compute_tile = [&](int stage) {
        const char* sA = smem + stage * STAGE_BYTES;
        const char* sB = sA + TILE_BYTES;
#pragma unroll
        for (int ks = 0; ks < 4; ks++) {
            uint4 af[4];
#pragma unroll
            for (int mt = 0; mt < 4; mt++)
                af[mt] = *(const uint4*)(sA + (((warp_m * 4 + mt) * 4 + ks) * 32 + lane) * 16);
            uint4 bv[2];
#pragma unroll
            for (int ntp = 0; ntp < 2; ntp++)
                bv[ntp] = *(const uint4*)(sB + (((warp_n * 2 + ntp) * 4 + ks) * 32 + lane) * 16);
            uint32_t bf[4][2];
#pragma unroll
            for (int ntp = 0; ntp < 2; ntp++) {
                bf[2 * ntp][0] = bv[ntp].x;
                bf[2 * ntp][1] = bv[ntp].y;
                bf[2 * ntp + 1][0] = bv[ntp].z;
                bf[2 * ntp + 1][1] = bv[ntp].w;
            }
#pragma unroll
            for (int mt = 0; mt < 4; mt++)
#pragma unroll
                for (int nt = 0; nt < 4; nt++)
                    mma_f16(acc[mt][nt], (const uint32_t*)&af[mt], bf[nt]);
        }
    };

    for (int kt = 0; kt < KT_CNT; kt++) {
        const int s = kt % STAGES;
        const int n = kt / STAGES;
        // producer: issue kt+2 into its stage once that stage is empty again
        if (tid == 0 && kt + 2 < KT_CNT) {
            const int kt2 = kt + 2;
            const int s2 = kt2 % STAGES;
            const int n2 = kt2 / STAGES;
            if (n2 > 0) MBAR_WAIT(bar0 + 24 + s2 * 8, (n2 - 1) & 1);
            issue_tile(s2, kt2);
        }
        MBAR_WAIT(bar0 + s * 8, n & 1);       // wait full (acquire)
        compute_tile(s);
        __syncwarp();
        if (lane == 0) MBAR_ARRIVE(bar0 + 24 + s * 8);   // release stage
    }

    // ---- pure-store epilogue (LoRA already folded into K) ----
#pragma unroll
    for (int mt = 0; mt < 4; mt++)
#pragma unroll
        for (int i = 0; i < 2; i++) {
            const size_t row = (size_t)mtile * 128 + warp_m * 64 + mt * 16 + g + i * 8;
#pragma unroll
            for (int nt = 0; nt < 4; nt++) {
                const uint32_t col = ntile * 128 + warp_n * 32 + nt * 8 + tg * 2;
                *(float2*)&out[row * N_DIM + col] =
                    make_float2(acc[mt][nt][i * 2 + 0], acc[mt][nt][i * 2 + 1]);
            }
        }
}

// ---------------------------------------------------------------------------
// Harness entry
// d_in[0]=data [8,2048,4096] f32, d_in[1]=W [4096,4096] f32,
// d_in[2]=lora_a [8,16,4096] f32, d_in[3]=lora_b [8,4096,16] f32
// ---------------------------------------------------------------------------
extern "C" void kernel_launch(void* const* d_in, const int* in_sizes, int n_in,
                              void* d_out, int out_size) {
    const float* x = (const float*)d_in[0];
    const float* W = (const float*)d_in[1];
    const float* la = (const float*)d_in[2];
    const float* lb = (const float*)d_in[3];
    float* out = (float*)d_out;

    cudaFuncSetAttribute(lora_gemm_kernel,
                         cudaFuncAttributeMaxDynamicSharedMemorySize, SMEM_BYTES);

    lora_t_kernel<<<M_DIM / 32, 256>>>(x, la);
    ext_a_kernel<<<(128 * KT_CNT * 1024) / 256, 256>>>(x);
    ext_b_kernel<<<(32 * KT_CNT * 1024) / 256, 256>>>(W, lb);

    dim3 grid(N_DIM / 128, M_DIM / 128);  // (32, 128)
    lora_gemm_kernel<<<grid, 256, SMEM_BYTES>>>(out);
}

// round 17
// speedup vs baseline: 1.7882x; 1.0202x over previous
#include <cuda_runtime.h>
#include <cuda_fp16.h>
#include <cstdint>

// ---------------------------------------------------------------------------
// Problem constants
// ---------------------------------------------------------------------------
#define M_DIM 16384   // B*S = 8*2048
#define N_DIM 4096    // OUT
#define K_DIM 4096    // IN
#define KE    4224    // extended K: 4096 + 8 adapters * 16 rank
#define BK    64
#define KT_CNT 66     // KE / 64
#define S_LEN 2048
#define R_RANK 16

// ---------------------------------------------------------------------------
// Device-global scratch
//  g_t  : t = x @ lora_a^T, fp32 [M, 16]
//  g_xe : A image, fp16 + K-extended + FRAGMENT-PACKED (m16n8k16 layout)
//         [mtile(128)][ktile(66)] x 16KB tiles (8192 halves)
//  g_we : B image likewise: [ntile(32)][ktile(66)] x 16KB tiles
// ---------------------------------------------------------------------------
__device__ __align__(16) float g_t[M_DIM * R_RANK];
__device__ __align__(1024) __half g_xe[(size_t)128 * KT_CNT * 8192];
__device__ __align__(1024) __half g_we[(size_t)32  * KT_CNT * 8192];

__device__ __forceinline__ uint32_t pack2(float lo, float hi) {
    __half2 h = __floats2half2_rn(lo, hi);
    return *(uint32_t*)&h;
}

// ---------------------------------------------------------------------------
// mbarrier / bulk-copy helpers (sm_90 features, sm_103-base legal)
// ---------------------------------------------------------------------------
#define MBAR_INIT(a, c) \
    asm volatile("mbarrier.init.shared.b64 [%0], %1;" :: "r"(a), "r"((uint32_t)(c)) : "memory")
#define MBAR_ARRIVE(a) \
    asm volatile("mbarrier.arrive.shared.b64 _, [%0];" :: "r"(a) : "memory")
#define MBAR_EXPECT_TX(a, b) \
    asm volatile("mbarrier.arrive.expect_tx.shared.b64 _, [%0], %1;" :: "r"(a), "r"((uint32_t)(b)) : "memory")
#define MBAR_WAIT(a, ph) do {                                                   \
    uint32_t _m = (a), _p = (uint32_t)(ph), _d;                                 \
    asm volatile("{\n\t.reg .pred p;\n\t"                                       \
        "mbarrier.try_wait.parity.acquire.cta.shared::cta.b64 p, [%1], %2;\n\t" \
        "selp.b32 %0, 1, 0, p;\n\t}" : "=r"(_d) : "r"(_m), "r"(_p) : "memory"); \
    if (!_d) {                                                                  \
        asm volatile("{\n\t.reg .pred P1;\n\tWL_%=:\n\t"                        \
            "mbarrier.try_wait.parity.acquire.cta.shared::cta.b64 P1, [%0], %1, 0x989680;\n\t" \
            "@P1 bra.uni WD_%=;\n\tbra.uni WL_%=;\n\tWD_%=:\n\t}"               \
            :: "r"(_m), "r"(_p) : "memory");                                    \
    }                                                                           \
} while (0)
#define BULK_G2S(dst, src, bytes, mbar)                                          \
    asm volatile(                                                                \
        "cp.async.bulk.shared::cta.global.mbarrier::complete_tx::bytes "         \
        "[%0], [%1], %2, [%3];"                                                  \
        :: "r"(dst), "l"(src), "r"((uint32_t)(bytes)), "r"(mbar) : "memory")

// ---------------------------------------------------------------------------
// Kernel 1: t[m, r] = sum_k x[m,k] * lora_a[adapter(m)][r][k]   (fp32 exact)
// (R5 verbatim — measured-good)
// ---------------------------------------------------------------------------
__global__ __launch_bounds__(256) void lora_t_kernel(const float* __restrict__ x,
                                                     const float* __restrict__ la) {
    const int warp = threadIdx.x >> 5;
    const int lane = threadIdx.x & 31;
    const int m0 = blockIdx.x * 32 + warp * 4;
    const int adapter = m0 / S_LEN;
    const float* lap = la + (size_t)adapter * R_RANK * K_DIM;

    float acc[4][R_RANK];
#pragma unroll
    for (int rr = 0; rr < 4; rr++)
#pragma unroll
        for (int r = 0; r < R_RANK; r++) acc[rr][r] = 0.f;

    for (int kk = lane; kk < K_DIM / 4; kk += 32) {
        const int k = kk * 4;
        float4 xv[4];
#pragma unroll
        for (int rr = 0; rr < 4; rr++)
            xv[rr] = *(const float4*)(x + (size_t)(m0 + rr) * K_DIM + k);
#pragma unroll
        for (int r = 0; r < R_RANK; r++) {
            const float4 av = *(const float4*)(lap + (size_t)r * K_DIM + k);
#pragma unroll
            for (int rr = 0; rr < 4; rr++) {
                acc[rr][r] += xv[rr].x * av.x;
                acc[rr][r] += xv[rr].y * av.y;
                acc[rr][r] += xv[rr].z * av.z;
                acc[rr][r] += xv[rr].w * av.w;
            }
        }
    }
#pragma unroll
    for (int off = 16; off > 0; off >>= 1)
#pragma unroll
        for (int rr = 0; rr < 4; rr++)
#pragma unroll
            for (int r = 0; r < R_RANK; r++)
                acc[rr][r] += __shfl_xor_sync(0xffffffffu, acc[rr][r], off);
    if (lane < R_RANK) {
#pragma unroll
        for (int rr = 0; rr < 4; rr++)
            g_t[(m0 + rr) * R_RANK + lane] = acc[rr][lane];
    }
}

// ---------------------------------------------------------------------------
// Kernel 2a: build A image, REAL-K ktiles only (no g_t dependency).
// one thread = one 16B unit (= one A fragment a0..a3). R11-verified indexing.
// ---------------------------------------------------------------------------
__global__ __launch_bounds__(256) void ext_a_realk_kernel(const float* __restrict__ x) {
    const uint32_t idx = blockIdx.x * 256 + threadIdx.x;  // < 128*64*1024
    const uint32_t u = idx & 1023;
    const uint32_t t2 = idx >> 10;                        // mtile*64 + ktile
    const uint32_t mtile = t2 >> 6;
    const uint32_t ktile = t2 & 63;

    const uint32_t lane = u & 31;
    const uint32_t ks = (u >> 5) & 3;
    const uint32_t mt = (u >> 7) & 3;
    const uint32_t wm = (u >> 9) & 1;
    const uint32_t g = lane >> 2, tg = lane & 3;

    const uint32_t m0 = mtile * 128 + wm * 64 + mt * 16 + g;  // rows m0, m0+8
    const uint32_t k0 = ktile * 64 + ks * 16 + 2 * tg;

    const float2 p00 = *(const float2*)(x + (size_t)m0 * K_DIM + k0);
    const float2 p10 = *(const float2*)(x + (size_t)(m0 + 8) * K_DIM + k0);
    const float2 p01 = *(const float2*)(x + (size_t)m0 * K_DIM + k0 + 8);
    const float2 p11 = *(const float2*)(x + (size_t)(m0 + 8) * K_DIM + k0 + 8);
    uint4 v;
    v.x = pack2(p00.x, p00.y);
    v.y = pack2(p10.x, p10.y);
    v.z = pack2(p01.x, p01.y);
    v.w = pack2(p11.x, p11.y);
    *(uint4*)(g_xe + (size_t)(mtile * KT_CNT + ktile) * 8192 + u * 8) = v;
}

// ---------------------------------------------------------------------------
// Kernel 2b: A-image extension tail (ktiles 64,65) — needs FINAL g_t.
// Tiny (256 blocks). R11-verified.
// ---------------------------------------------------------------------------
__global__ __launch_bounds__(256) void ext_a_tail_kernel() {
    const int tid = threadIdx.x;
    const uint32_t kt = 64 + blockIdx.x;    // 64 or 65
    const uint32_t mtile = blockIdx.y;

    __half* dst = g_xe + (size_t)(mtile * KT_CNT + kt) * 8192;
#pragma unroll
    for (int j = 0; j < 4; j++) {
        const uint32_t u = tid + j * 256;
        const uint32_t lane = u & 31;
        const uint32_t ks = (u >> 5) & 3;
        const uint32_t mt = (u >> 7) & 3;
        const uint32_t wm = (u >> 9) & 1;
        const uint32_t g = lane >> 2, tg = lane & 3;

        const uint32_t m0 = mtile * 128 + wm * 64 + mt * 16 + g;
        const uint32_t k0 = kt * 64 + ks * 16 + 2 * tg;
        const uint32_t e = k0 - K_DIM;      // pairs stay inside one 16-chunk
        const uint32_t a = e >> 4, r = e & 15;
        const uint32_t ad = m0 >> 11;

        uint4 v = make_uint4(0, 0, 0, 0);
        if (a == ad) {
            const float2 t00 = *(const float2*)(g_t + (size_t)m0 * R_RANK + r);
            const float2 t10 = *(const float2*)(g_t + (size_t)(m0 + 8) * R_RANK + r);
            const float2 t01 = *(const float2*)(g_t + (size_t)m0 * R_RANK + r + 8);
            const float2 t11 = *(const float2*)(g_t + (size_t)(m0 + 8) * R_RANK + r + 8);
            v.x = pack2(2.f * t00.x, 2.f * t00.y);
            v.y = pack2(2.f * t10.x, 2.f * t10.y);
            v.z = pack2(2.f * t01.x, 2.f * t01.y);
            v.w = pack2(2.f * t11.x, 2.f * t11.y);
        }
        *(uint4*)(dst + u * 8) = v;
    }
}

// ---------------------------------------------------------------------------
// Kernel 3: build B image (R5 verbatim — measured-good)
// ---------------------------------------------------------------------------
__global__ __launch_bounds__(256) void ext_b_kernel(const float* __restrict__ W,
                                                    const float* __restrict__ lb) {
    const uint32_t idx = blockIdx.x * 256 + threadIdx.x;  // < 32*66*1024
    const uint32_t u = idx & 1023;
    const uint32_t tile = idx >> 10;
    const uint32_t ntile = tile / KT_CNT;
    const uint32_t ktile = tile % KT_CNT;

    const uint32_t lane = u & 31;
    const uint32_t ks = (u >> 5) & 3;
    const uint32_t ntp = (u >> 7) & 1;
    const uint32_t wn = (u >> 8) & 3;
    const uint32_t g = lane >> 2, tg = lane & 3;

    const uint32_t c0 = ntile * 128 + wn * 32 + ntp * 16 + g;  // cols c0, c0+8
    const uint32_t k0 = ktile * 64 + ks * 16 + 2 * tg;

    uint4 v;
    if (k0 < K_DIM) {
        const float2 p00 = *(const float2*)(W + (size_t)c0 * K_DIM + k0);
        const float2 p01 = *(const float2*)(W + (size_t)c0 * K_DIM + k0 + 8);
        const float2 p10 = *(const float2*)(W + (size_t)(c0 + 8) * K_DIM + k0);
        const float2 p11 = *(const float2*)(W + (size_t)(c0 + 8) * K_DIM + k0 + 8);
        v.x = pack2(p00.x, p00.y);
        v.y = pack2(p01.x, p01.y);
        v.z = pack2(p10.x, p10.y);
        v.w = pack2(p11.x, p11.y);
    } else {
        const uint32_t e = k0 - K_DIM;
        const uint32_t a = e >> 4, r = e & 15;
        const float* p0 = lb + ((size_t)a * N_DIM + c0) * R_RANK;
        const float* p1 = lb + ((size_t)a * N_DIM + c0 + 8) * R_RANK;
        v.x = pack2(p0[r], p0[r + 1]);
        v.y = pack2(p0[r + 8], p0[r + 9]);
        v.z = pack2(p1[r], p1[r + 1]);
        v.w = pack2(p1[r + 8], p1[r + 9]);
    }
    *(uint4*)(g_we + (size_t)tile * 8192 + u * 8) = v;
}

// ---------------------------------------------------------------------------
// Kernel 4: GEMM — R15 verbatim (measured 1061us, tensor 88.5%).
// 128x128x64 tiles, fp16 m16n8k16 (f32 accum), fragment-packed smem,
// 3-stage cp.async.bulk + mbarrier pipeline, 2 CTAs/SM.
// ---------------------------------------------------------------------------
#define STAGES 3
#define TILE_BYTES 16384
#define STAGE_BYTES (2 * TILE_BYTES)               // A + B = 32KB
#define BAR_BYTES 64
#define SMEM_BYTES (STAGES * STAGE_BYTES + BAR_BYTES)   // 98368

__device__ __forceinline__ void mma_f16(float* c, const uint32_t* a, const uint32_t* b) {
    asm volatile(
        "mma.sync.aligned.m16n8k16.row.col.f32.f16.f16.f32 "
        "{%0,%1,%2,%3}, {%4,%5,%6,%7}, {%8,%9}, {%0,%1,%2,%3};"
        : "+f"(c[0]), "+f"(c[1]), "+f"(c[2]), "+f"(c[3])
        : "r"(a[0]), "r"(a[1]), "r"(a[2]), "r"(a[3]), "r"(b[0]), "r"(b[1]));
}

__global__ __launch_bounds__(256, 2) void lora_gemm_kernel(float* __restrict__ out) {
    extern __shared__ char smem[];
    const int tid = threadIdx.x;
    const int lane = tid & 31;
    const int warp = tid >> 5;
    const int warp_m = warp >> 2;   // 0..1
    const int warp_n = warp & 3;    // 0..3
    const int g = lane >> 2;
    const int tg = lane & 3;
    const uint32_t mtile = blockIdx.y;
    const uint32_t ntile = blockIdx.x;

    const uint32_t bar0 = (uint32_t)__cvta_generic_to_shared(smem + STAGES * STAGE_BYTES);
    // full[s] = bar0 + s*8 ; empty[s] = bar0 + 24 + s*8

    float acc[4][4][4];
#pragma unroll
    for (int mt = 0; mt < 4; mt++)
#pragma unroll
        for (int nt = 0; nt < 4; nt++)
#pragma unroll
            for (int c = 0; c < 4; c++) acc[mt][nt][c] = 0.f;

    const char* gA = (const char*)g_xe + ((size_t)mtile * KT_CNT << 14);
    const char* gB = (const char*)g_we + ((size_t)ntile * KT_CNT << 14);

    if (tid == 0) {
#pragma unroll
        for (int s = 0; s < STAGES; s++) {
            MBAR_INIT(bar0 + s * 8, 1);        // full: 1 expect_tx arrival
            MBAR_INIT(bar0 + 24 + s * 8, 8);   // empty: one arrive per warp
        }
    }
    __syncthreads();

    auto issue_tile = [&](int s, int kt) {
        const uint32_t full = bar0 + s * 8;
        const uint32_t st = (uint32_t)__cvta_generic_to_shared(smem + s * STAGE_BYTES);
        MBAR_EXPECT_TX(full, STAGE_BYTES);
        BULK_G2S(st, gA + ((size_t)kt << 14), TILE_BYTES, full);
        BULK_G2S(st + TILE_BYTES, gB + ((size_t)kt << 14), TILE_BYTES, full);
    };

    if (tid == 0) {
        issue_tile(0, 0);
        issue_tile(1, 1);
    }

    auto compute_tile = [&](int stage) {
        const char* sA = smem + stage * STAGE_BYTES;
        const char* sB = sA + TILE_BYTES;
#pragma unroll
        for (int ks = 0; ks < 4; ks++) {
            uint4 af[4];
#pragma unroll
            for (int mt = 0; mt < 4; mt++)
                af[mt] = *(const uint4*)(sA + (((warp_m * 4 + mt) * 4 + ks) * 32 + lane) * 16);
            uint4 bv[2];
#pragma unroll
            for (int ntp = 0; ntp < 2; ntp++)
                bv[ntp] = *(const uint4*)(sB + (((warp_n * 2 + ntp) * 4 + ks) * 32 + lane) * 16);
            uint32_t bf[4][2];
#pragma unroll
            for (int ntp = 0; ntp < 2; ntp++) {
                bf[2 * ntp][0] = bv[ntp].x;
                bf[2 * ntp][1] = bv[ntp].y;
                bf[2 * ntp + 1][0] = bv[ntp].z;
                bf[2 * ntp + 1][1] = bv[ntp].w;
            }
#pragma unroll
            for (int mt = 0; mt < 4; mt++)
#pragma unroll
                for (int nt = 0; nt < 4; nt++)
                    mma_f16(acc[mt][nt], (const uint32_t*)&af[mt], bf[nt]);
        }
    };

    for (int kt = 0; kt < KT_CNT; kt++) {
        const int s = kt % STAGES;
        const int n = kt / STAGES;
        if (tid == 0 && kt + 2 < KT_CNT) {
            const int kt2 = kt + 2;
            const int s2 = kt2 % STAGES;
            const int n2 = kt2 / STAGES;
            if (n2 > 0) MBAR_WAIT(bar0 + 24 + s2 * 8, (n2 - 1) & 1);
            issue_tile(s2, kt2);
        }
        MBAR_WAIT(bar0 + s * 8, n & 1);       // wait full (acquire)
        compute_tile(s);
        __syncwarp();
        if (lane == 0) MBAR_ARRIVE(bar0 + 24 + s * 8);   // release stage
    }

    // ---- pure-store epilogue (LoRA already folded into K) ----
#pragma unroll
    for (int mt = 0; mt < 4; mt++)
#pragma unroll
        for (int i = 0; i < 2; i++) {
            const size_t row = (size_t)mtile * 128 + warp_m * 64 + mt * 16 + g + i * 8;
#pragma unroll
            for (int nt = 0; nt < 4; nt++) {
                const uint32_t col = ntile * 128 + warp_n * 32 + nt * 8 + tg * 2;
                *(float2*)&out[row * N_DIM + col] =
                    make_float2(acc[mt][nt][i * 2 + 0], acc[mt][nt][i * 2 + 1]);
            }
        }
}

// ---------------------------------------------------------------------------
// Harness entry — prepass forked across 3 streams (graph-capture fork/join):
//   stream0: lora_t -> ext_a_tail        (tail needs final g_t)
//   stream1: ext_a_realk                 (independent)
//   stream2: ext_b                       (independent)
//   join -> GEMM
// Streams/events created per call (graph replays don't re-run host code).
// ---------------------------------------------------------------------------
extern "C" void kernel_launch(void* const* d_in, const int* in_sizes, int n_in,
                              void* d_out, int out_size) {
    const float* x = (const float*)d_in[0];
    const float* W = (const float*)d_in[1];
    const float* la = (const float*)d_in[2];
    const float* lb = (const float*)d_in[3];
    float* out = (float*)d_out;

    cudaFuncSetAttribute(lora_gemm_kernel,
                         cudaFuncAttributeMaxDynamicSharedMemorySize, SMEM_BYTES);

    cudaStream_t s1, s2;
    cudaStreamCreateWithFlags(&s1, cudaStreamNonBlocking);
    cudaStreamCreateWithFlags(&s2, cudaStreamNonBlocking);
    cudaEvent_t e0, e1, e2;
    cudaEventCreateWithFlags(&e0, cudaEventDisableTiming);
    cudaEventCreateWithFlags(&e1, cudaEventDisableTiming);
    cudaEventCreateWithFlags(&e2, cudaEventDisableTiming);

    // fork
    cudaEventRecord(e0, 0);
    cudaStreamWaitEvent(s1, e0, 0);
    cudaStreamWaitEvent(s2, e0, 0);

    lora_t_kernel<<<M_DIM / 32, 256, 0, 0>>>(x, la);
    {
        dim3 gt(2, M_DIM / 128);
        ext_a_tail_kernel<<<gt, 256, 0, 0>>>();
    }
    ext_a_realk_kernel<<<(128 * 64 * 1024) / 256, 256, 0, s1>>>(x);
    ext_b_kernel<<<(32 * KT_CNT * 1024) / 256, 256, 0, s2>>>(W, lb);

    // join
    cudaEventRecord(e1, s1);
    cudaEventRecord(e2, s2);
    cudaStreamWaitEvent(0, e1, 0);
    cudaStreamWaitEvent(0, e2, 0);

    dim3 grid(N_DIM / 128, M_DIM / 128);  // (32, 128)
    lora_gemm_kernel<<<grid, 256, SMEM_BYTES>>>(out);

    cudaEventDestroy(e0);
    cudaEventDestroy(e1);
    cudaEventDestroy(e2);
    cudaStreamDestroy(s1);
    cudaStreamDestroy(s2);
}